// round 12
// baseline (speedup 1.0000x reference)
#include <cuda_runtime.h>
#include <cuda_bf16.h>
#include <cstdint>

#define K_DIM 512
#define O_DIM 8
#define JX    4096
#define SZ    (K_DIM * K_DIM * O_DIM)

// ---------------- scratch (no allocations allowed) ----------------
__device__ __nv_bfloat16 g_Abf[(size_t)JX * K_DIM];   // A'[(j,x)][k] * Pb[j]*Pc[k]
__device__ __nv_bfloat16 g_Bbf[(size_t)JX * K_DIM];   // B'[(i,y)][k] * Pa[i]
__device__ float g_partial[1024 * 512];               // per-CTA probs partials
__device__ float g_partial2[16 * 512];                // stage-2 partials

__device__ __forceinline__ uint32_t smem_u32(const void* p) {
    return (uint32_t)__cvta_generic_to_shared(p);
}
__device__ __forceinline__ void cp_async16(uint32_t dst, const void* src) {
    asm volatile("cp.async.cg.shared.global [%0], [%1], 16;" :: "r"(dst), "l"(src));
}
__device__ __forceinline__ void cp_commit() { asm volatile("cp.async.commit_group;" ::: "memory"); }
template <int N> __device__ __forceinline__ void cp_wait() {
    asm volatile("cp.async.wait_group %0;" :: "n"(N) : "memory");
}

// ---------------- fused conversions (one launch) -----------------------------
// blocks [0,512):   A[j,k,x]*Pb[j]*Pc[k] -> g_Abf[(j*8+x)][k]
// blocks [512,2560): B[k][iy]*Pa[iy>>3]  -> g_Bbf[iy][k]  (32x32 transpose tiles)
__global__ void conv_kernel(const float* __restrict__ y) {
    __shared__ float sbuf[K_DIM * 9];     // 18.4KB, covers both uses
    if (blockIdx.x < 512) {
        const float* Pb = y + 512;
        const float* Pc = y + 1024;
        const float* A  = y + 1536;
        int j = blockIdx.x;
        float pb = Pb[j];
        const float* Aj = A + (size_t)j * (K_DIM * O_DIM);
        for (int t = threadIdx.x; t < K_DIM * O_DIM; t += blockDim.x) {
            int k = t >> 3, x = t & 7;
            sbuf[k * 9 + x] = Aj[t];                 // coalesced read
        }
        __syncthreads();
        for (int t = threadIdx.x; t < K_DIM * O_DIM; t += blockDim.x) {
            int x = t >> 9, k = t & 511;
            float v = sbuf[k * 9 + x] * pb * Pc[k];
            g_Abf[(size_t)(j * 8 + x) * K_DIM + k] = __float2bfloat16_rn(v);
        }
    } else {
        const float* Pa = y;
        const float* B  = y + 1536 + SZ;
        float (*tile)[33] = (float(*)[33])sbuf;
        int b2 = blockIdx.x - 512;
        int iy0 = (b2 & 127) * 32;     // over 4096
        int k0  = (b2 >> 7) * 32;      // over 512
        int c = threadIdx.x & 31;
        int r0 = threadIdx.x >> 5;     // 0..7
#pragma unroll
        for (int s = 0; s < 4; s++) {
            int r = r0 + s * 8;
            tile[r][c] = B[(size_t)(k0 + r) * JX + iy0 + c];
        }
        __syncthreads();
#pragma unroll
        for (int s = 0; s < 4; s++) {
            int r = r0 + s * 8;
            int iy = iy0 + r;
            float v = tile[c][r] * Pa[iy >> 3];
            g_Bbf[(size_t)iy * K_DIM + k0 + c] = __float2bfloat16_rn(v);
        }
    }
}

// ================= pipelined GEMM (mma.sync bf16) + fused epilogue ===========
// SMEM: [0,8192) Cs (epilogue C block) | [8192, +3*36864) 3-stage A/B ring
//       warpP (epilogue) reuses the stage region after the mainloop.
#define SM_C     0
#define SM_STAGE 8192
#define STAGE_SZ 36864       // A: 128x72 bf16 (18432B) + B: 128x72 bf16
#define SMEM_DYN (SM_STAGE + 3 * STAGE_SZ)   // 118784 bytes

__global__ void __launch_bounds__(256, 1) gemm_kernel(const float* __restrict__ y) {
    extern __shared__ __align__(128) unsigned char sm[];
    const float* C = y + 1536 + 2 * (size_t)SZ;
    const uint32_t smb = smem_u32(sm);
    const int tid  = threadIdx.x;
    const int lane = tid & 31, wid = tid >> 5;
    const int wm = wid & 3;       // 4 row-groups of 32
    const int wn = wid >> 2;      // 2 col-groups of 64
    const int bm = blockIdx.x, bn = blockIdx.y;

    float* Cs    = (float*)(sm + SM_C);
    float* warpP = (float*)(sm + SM_STAGE);   // valid after mainloop drains

    // ---- cp.async chunk loader: chunk c (64 k-cols) into stage st ----
    auto load_chunk = [&](int c, int st) {
        uint32_t base = smb + SM_STAGE + st * STAGE_SZ;
#pragma unroll
        for (int s = 0; s < 4; s++) {
            int q = tid + s * 256;
            int row = q >> 3, c16 = q & 7;
            uint32_t off = (uint32_t)(row * 72 + c16 * 8) * 2;   // 16B aligned (144-stride)
            const __nv_bfloat16* ga = g_Abf + (size_t)(bm * 128 + row) * K_DIM + c * 64 + c16 * 8;
            cp_async16(base + off, ga);
            const __nv_bfloat16* gb = g_Bbf + (size_t)(bn * 128 + row) * K_DIM + c * 64 + c16 * 8;
            cp_async16(base + 18432 + off, gb);
        }
        cp_commit();
    };

    // prologue: C block rides in chunk-0's commit group
    {
        int il = tid >> 4, jl = tid & 15;
        const float* src = C + ((size_t)(bn * 16 + il) * K_DIM + (bm * 16 + jl)) * 8;
        uint32_t dst = smb + SM_C + (uint32_t)(il * 16 + jl) * 32;
        cp_async16(dst, src);
        cp_async16(dst + 16, src + 4);
    }
    load_chunk(0, 0);
    load_chunk(1, 1);

    float acc[2][8][4];
#pragma unroll
    for (int a = 0; a < 2; a++)
#pragma unroll
        for (int b = 0; b < 8; b++)
#pragma unroll
            for (int c = 0; c < 4; c++) acc[a][b][c] = 0.f;

    // ---- mainloop: 8 K-chunks, 3-stage ring, prefetch distance 2 ----
    for (int i = 0; i < 8; i++) {
        const int st = i - (i >= 3 ? 3 : 0) - (i >= 6 ? 3 : 0);  // i % 3
        if (i == 7) cp_wait<0>(); else cp_wait<1>();
        __syncthreads();                       // chunk i visible; chunk i-1 compute done chip-wide
        if (i < 6) load_chunk(i + 2, (st + 2 >= 3) ? st - 1 : st + 2);

        __nv_bfloat16* As = (__nv_bfloat16*)(sm + SM_STAGE + st * STAGE_SZ);
        __nv_bfloat16* Bs = As + 128 * 72;
#pragma unroll
        for (int ks = 0; ks < 64; ks += 16) {
            uint32_t a[2][4];
#pragma unroll
            for (int mt = 0; mt < 2; mt++) {
                uint32_t addr = smem_u32(As + (wm * 32 + mt * 16 + (lane & 15)) * 72
                                            + ks + (lane >> 4) * 8);
                asm volatile("ldmatrix.sync.aligned.m8n8.x4.shared.b16 {%0,%1,%2,%3}, [%4];"
                             : "=r"(a[mt][0]), "=r"(a[mt][1]), "=r"(a[mt][2]), "=r"(a[mt][3])
                             : "r"(addr));
            }
            uint32_t b[4][4];
#pragma unroll
            for (int p = 0; p < 4; p++) {
                uint32_t addr = smem_u32(Bs + (wn * 64 + p * 16 + ((lane >> 3) & 1) * 8 + (lane & 7)) * 72
                                            + ks + (lane >> 4) * 8);
                asm volatile("ldmatrix.sync.aligned.m8n8.x4.shared.b16 {%0,%1,%2,%3}, [%4];"
                             : "=r"(b[p][0]), "=r"(b[p][1]), "=r"(b[p][2]), "=r"(b[p][3])
                             : "r"(addr));
            }
#pragma unroll
            for (int mt = 0; mt < 2; mt++)
#pragma unroll
                for (int nt = 0; nt < 8; nt++) {
                    const int p = nt >> 1, h = nt & 1;
                    asm volatile(
                        "mma.sync.aligned.m16n8k16.row.col.f32.bf16.bf16.f32 "
                        "{%0,%1,%2,%3}, {%4,%5,%6,%7}, {%8,%9}, {%0,%1,%2,%3};"
                        : "+f"(acc[mt][nt][0]), "+f"(acc[mt][nt][1]),
                          "+f"(acc[mt][nt][2]), "+f"(acc[mt][nt][3])
                        : "r"(a[mt][0]), "r"(a[mt][1]), "r"(a[mt][2]), "r"(a[mt][3]),
                          "r"(b[p][h]), "r"(b[p][2 + h]));
                }
        }
    }
    __syncthreads();   // everyone done with stages -> warpP region reusable

    // ---- epilogue: acc x Cs -> per-warp probs partials (identical to R5) ----
    float pl[2][8];
#pragma unroll
    for (int z = 0; z < 8; z++) { pl[0][z] = 0.f; pl[1][z] = 0.f; }

#pragma unroll
    for (int mt = 0; mt < 2; mt++)
#pragma unroll
        for (int hh = 0; hh < 2; hh++) {
            const int jl = wm * 4 + mt * 2 + hh;
#pragma unroll
            for (int nt = 0; nt < 8; nt++) {
                const int il = wn * 8 + nt;
                const float* crow = Cs + (il * 16 + jl) * 8;   // warp-broadcast
                const float d0 = acc[mt][nt][hh * 2 + 0];
                const float d1 = acc[mt][nt][hh * 2 + 1];
#pragma unroll
                for (int z = 0; z < 8; z++) {
                    float cz = crow[z];
                    pl[0][z] += d0 * cz;
                    pl[1][z] += d1 * cz;
                }
            }
        }

    {
        const int x = lane >> 2, yb = (lane & 3) * 2;
        float* wp = warpP + wid * 512 + x * 64 + yb * 8;
#pragma unroll
        for (int z = 0; z < 8; z++) { wp[z] = pl[0][z]; wp[8 + z] = pl[1][z]; }
    }
    __syncthreads();

    // fixed-order cross-warp reduce -> deterministic per-CTA partial
    const int ctaId = bn * gridDim.x + bm;
    for (int e = tid; e < 512; e += 256) {
        float s = 0.f;
#pragma unroll
        for (int w = 0; w < 8; w++) s += warpP[w * 512 + e];
        g_partial[(size_t)ctaId * 512 + e] = s;
    }
}

// ---------------- deterministic reductions ----------------
// 64 blocks x 128 thr: block b -> e = (b&3)*128+tid, ctas [(b>>2)*64, +64)
__global__ void reduce_stage_kernel() {
    int e = (blockIdx.x & 3) * 128 + threadIdx.x;
    int cg = blockIdx.x >> 2;              // 0..15
    float s = 0.f;
    for (int c = cg * 64; c < cg * 64 + 64; c++)
        s += g_partial[(size_t)c * 512 + e];
    g_partial2[cg * 512 + e] = s;
}

__global__ void finalize_kernel(const float* __restrict__ y_true, float* __restrict__ out) {
    __shared__ float red[512];
    int e = threadIdx.x;       // 512
    float s = 0.f;
#pragma unroll
    for (int b = 0; b < 16; b++) s += g_partial2[b * 512 + e];
    out[1 + e] = s;                                   // probs
    float p = fminf(fmaxf(s, 1e-10f), 1.0f);          // clip
    float t = y_true[e];
    red[e] = t * (logf(t + 1e-10f) - logf(p));
    __syncthreads();
    for (int st = 256; st > 0; st >>= 1) {
        if (e < st) red[e] += red[e + st];
        __syncthreads();
    }
    if (e == 0) out[0] = red[0];                      // d
}

// ---------------- launch ----------------
extern "C" void kernel_launch(void* const* d_in, const int* in_sizes, int n_in,
                              void* d_out, int out_size) {
    const float* y_pred = (const float*)d_in[0];
    const float* y_true = (const float*)d_in[1];
    float* out = (float*)d_out;

    cudaFuncSetAttribute(gemm_kernel, cudaFuncAttributeMaxDynamicSharedMemorySize, SMEM_DYN);

    conv_kernel<<<2560, 256>>>(y_pred);
    gemm_kernel<<<dim3(32, 32), 256, SMEM_DYN>>>(y_pred);
    reduce_stage_kernel<<<64, 128>>>();
    finalize_kernel<<<1, 512>>>(y_true, out);
}

// round 17
// speedup vs baseline: 1.3320x; 1.3320x over previous
#include <cuda_runtime.h>
#include <cuda_bf16.h>
#include <cstdint>

#define K_DIM 512
#define O_DIM 8
#define JX    4096
#define SZ    (K_DIM * K_DIM * O_DIM)

// ---------------- scratch (no allocations allowed) ----------------
__device__ __nv_bfloat16 g_Abf[(size_t)JX * K_DIM];   // A'[(j,x)][k] * Pb[j]*Pc[k]
__device__ __nv_bfloat16 g_Bbf[(size_t)JX * K_DIM];   // B'[(i,y)][k] * Pa[i]
__device__ float g_partial[1024 * 512];               // per-CTA probs partials
__device__ float g_partial2[16 * 512];                // stage-2 partials
__device__ unsigned int g_cnt;                        // last-block ticket (self-resetting)

__device__ __forceinline__ uint32_t smem_u32(const void* p) {
    return (uint32_t)__cvta_generic_to_shared(p);
}
__device__ __forceinline__ void cp_async16(uint32_t dst, const void* src) {
    asm volatile("cp.async.cg.shared.global [%0], [%1], 16;" :: "r"(dst), "l"(src));
}
__device__ __forceinline__ void cp_commit() { asm volatile("cp.async.commit_group;" ::: "memory"); }
template <int N> __device__ __forceinline__ void cp_wait() {
    asm volatile("cp.async.wait_group %0;" :: "n"(N) : "memory");
}

// ---------------- fused conversions (one launch) -----------------------------
__global__ void conv_kernel(const float* __restrict__ y) {
    __shared__ float sbuf[K_DIM * 9];     // 18.4KB, covers both uses
    if (blockIdx.x < 512) {
        const float* Pb = y + 512;
        const float* Pc = y + 1024;
        const float* A  = y + 1536;
        int j = blockIdx.x;
        float pb = Pb[j];
        const float* Aj = A + (size_t)j * (K_DIM * O_DIM);
        for (int t = threadIdx.x; t < K_DIM * O_DIM; t += blockDim.x) {
            int k = t >> 3, x = t & 7;
            sbuf[k * 9 + x] = Aj[t];                 // coalesced read
        }
        __syncthreads();
        for (int t = threadIdx.x; t < K_DIM * O_DIM; t += blockDim.x) {
            int x = t >> 9, k = t & 511;
            float v = sbuf[k * 9 + x] * pb * Pc[k];
            g_Abf[(size_t)(j * 8 + x) * K_DIM + k] = __float2bfloat16_rn(v);
        }
    } else {
        const float* Pa = y;
        const float* B  = y + 1536 + SZ;
        float (*tile)[33] = (float(*)[33])sbuf;
        int b2 = blockIdx.x - 512;
        int iy0 = (b2 & 127) * 32;     // over 4096
        int k0  = (b2 >> 7) * 32;      // over 512
        int c = threadIdx.x & 31;
        int r0 = threadIdx.x >> 5;     // 0..7
#pragma unroll
        for (int s = 0; s < 4; s++) {
            int r = r0 + s * 8;
            tile[r][c] = B[(size_t)(k0 + r) * JX + iy0 + c];
        }
        __syncthreads();
#pragma unroll
        for (int s = 0; s < 4; s++) {
            int r = r0 + s * 8;
            int iy = iy0 + r;
            float v = tile[c][r] * Pa[iy >> 3];
            g_Bbf[(size_t)iy * K_DIM + k0 + c] = __float2bfloat16_rn(v);
        }
    }
}

// ================= pipelined GEMM (mma.sync bf16) + fused epilogue ===========
// SMEM: [0,8192) Cs | [8192, +2*32768) double-buffered A/B stages (swizzled
// 128B rows, no padding).  warpP reuses the stage region after the mainloop.
// 73728 B/CTA -> 2 CTAs/SM (cross-CTA overlap) + cp.async double buffering.
#define SM_C     0
#define SM_STAGE 8192
#define STAGE_SZ 32768       // A: 128 rows x 128B (16KB) + B: same
#define SMEM_DYN (SM_STAGE + 2 * STAGE_SZ)   // 73728 bytes

__global__ void __launch_bounds__(256, 2) gemm_kernel(const float* __restrict__ y) {
    extern __shared__ __align__(128) unsigned char sm[];
    const float* C = y + 1536 + 2 * (size_t)SZ;
    const uint32_t smb = smem_u32(sm);
    const int tid  = threadIdx.x;
    const int lane = tid & 31, wid = tid >> 5;
    const int wm = wid & 3;       // 4 row-groups of 32
    const int wn = wid >> 2;      // 2 col-groups of 64
    const int bm = blockIdx.x, bn = blockIdx.y;

    float* Cs    = (float*)(sm + SM_C);
    float* warpP = (float*)(sm + SM_STAGE);   // valid after mainloop drains

    // ---- cp.async chunk loader: chunk c (64 k-cols) into stage st ----
    // swizzle: 16B group column c16 XOR (row & 7) -> conflict-free ldmatrix
    auto load_chunk = [&](int c, int st) {
        uint32_t base = smb + SM_STAGE + st * STAGE_SZ;
#pragma unroll
        for (int s = 0; s < 4; s++) {
            int q = tid + s * 256;
            int row = q >> 3, c16 = q & 7;
            uint32_t off = (uint32_t)(row * 128 + ((c16 ^ (row & 7)) * 16));
            const __nv_bfloat16* ga = g_Abf + (size_t)(bm * 128 + row) * K_DIM + c * 64 + c16 * 8;
            cp_async16(base + off, ga);
            const __nv_bfloat16* gb = g_Bbf + (size_t)(bn * 128 + row) * K_DIM + c * 64 + c16 * 8;
            cp_async16(base + 16384 + off, gb);
        }
        cp_commit();
    };

    // prologue: C block rides in chunk-0's commit group
    {
        int il = tid >> 4, jl = tid & 15;
        const float* src = C + ((size_t)(bn * 16 + il) * K_DIM + (bm * 16 + jl)) * 8;
        uint32_t dst = smb + SM_C + (uint32_t)(il * 16 + jl) * 32;
        cp_async16(dst, src);
        cp_async16(dst + 16, src + 4);
    }
    load_chunk(0, 0);
    load_chunk(1, 1);

    float acc[2][8][4];
#pragma unroll
    for (int a = 0; a < 2; a++)
#pragma unroll
        for (int b = 0; b < 8; b++)
#pragma unroll
            for (int c = 0; c < 4; c++) acc[a][b][c] = 0.f;

    // ---- mainloop: 8 K-chunks, double buffer ----
    for (int i = 0; i < 8; i++) {
        const int st = i & 1;
        if (i == 7) cp_wait<0>(); else cp_wait<1>();
        __syncthreads();                       // chunk i resident

        const uint32_t As = smb + SM_STAGE + st * STAGE_SZ;
        const uint32_t Bs = As + 16384;
#pragma unroll
        for (int ks = 0; ks < 64; ks += 16) {
            const int kc = (ks >> 3);
            uint32_t a[2][4];
#pragma unroll
            for (int mt = 0; mt < 2; mt++) {
                int row = wm * 32 + mt * 16 + (lane & 15);
                int c16 = kc + (lane >> 4);
                uint32_t addr = As + row * 128 + ((c16 ^ (row & 7)) * 16);
                asm volatile("ldmatrix.sync.aligned.m8n8.x4.shared.b16 {%0,%1,%2,%3}, [%4];"
                             : "=r"(a[mt][0]), "=r"(a[mt][1]), "=r"(a[mt][2]), "=r"(a[mt][3])
                             : "r"(addr));
            }
            uint32_t b[4][4];
#pragma unroll
            for (int p = 0; p < 4; p++) {
                int row = wn * 64 + p * 16 + ((lane >> 3) & 1) * 8 + (lane & 7);
                int c16 = kc + (lane >> 4);
                uint32_t addr = Bs + row * 128 + ((c16 ^ (row & 7)) * 16);
                asm volatile("ldmatrix.sync.aligned.m8n8.x4.shared.b16 {%0,%1,%2,%3}, [%4];"
                             : "=r"(b[p][0]), "=r"(b[p][1]), "=r"(b[p][2]), "=r"(b[p][3])
                             : "r"(addr));
            }
#pragma unroll
            for (int mt = 0; mt < 2; mt++)
#pragma unroll
                for (int nt = 0; nt < 8; nt++) {
                    const int p = nt >> 1, h = nt & 1;
                    asm volatile(
                        "mma.sync.aligned.m16n8k16.row.col.f32.bf16.bf16.f32 "
                        "{%0,%1,%2,%3}, {%4,%5,%6,%7}, {%8,%9}, {%0,%1,%2,%3};"
                        : "+f"(acc[mt][nt][0]), "+f"(acc[mt][nt][1]),
                          "+f"(acc[mt][nt][2]), "+f"(acc[mt][nt][3])
                        : "r"(a[mt][0]), "r"(a[mt][1]), "r"(a[mt][2]), "r"(a[mt][3]),
                          "r"(b[p][h]), "r"(b[p][2 + h]));
                }
        }
        __syncthreads();                       // all warps done with stage st
        if (i < 6) load_chunk(i + 2, st);      // refill the stage just drained
    }

    // ---- epilogue: acc x Cs -> per-warp probs partials (proven R5 layout) ----
    float pl[2][8];
#pragma unroll
    for (int z = 0; z < 8; z++) { pl[0][z] = 0.f; pl[1][z] = 0.f; }

#pragma unroll
    for (int mt = 0; mt < 2; mt++)
#pragma unroll
        for (int hh = 0; hh < 2; hh++) {
            const int jl = wm * 4 + mt * 2 + hh;
#pragma unroll
            for (int nt = 0; nt < 8; nt++) {
                const int il = wn * 8 + nt;
                const float* crow = Cs + (il * 16 + jl) * 8;   // warp-broadcast
                const float d0 = acc[mt][nt][hh * 2 + 0];
                const float d1 = acc[mt][nt][hh * 2 + 1];
#pragma unroll
                for (int z = 0; z < 8; z++) {
                    float cz = crow[z];
                    pl[0][z] += d0 * cz;
                    pl[1][z] += d1 * cz;
                }
            }
        }

    {
        const int x = lane >> 2, yb = (lane & 3) * 2;
        float* wp = warpP + wid * 512 + x * 64 + yb * 8;
#pragma unroll
        for (int z = 0; z < 8; z++) { wp[z] = pl[0][z]; wp[8 + z] = pl[1][z]; }
    }
    __syncthreads();

    // fixed-order cross-warp reduce -> deterministic per-CTA partial
    const int ctaId = bn * gridDim.x + bm;
    for (int e = tid; e < 512; e += 256) {
        float s = 0.f;
#pragma unroll
        for (int w = 0; w < 8; w++) s += warpP[w * 512 + e];
        g_partial[(size_t)ctaId * 512 + e] = s;
    }
}

// ---------- merged deterministic reduction + finalize (last-block ticket) ----
// 64 blocks x 128 thr: block b handles e = (b&3)*128+tid for cta-group b>>2.
// Last block to finish sums the 16 stage-2 partials (fixed order) + computes d.
__global__ void reduce_final_kernel(const float* __restrict__ y_true,
                                    float* __restrict__ out) {
    __shared__ float red[128];
    __shared__ unsigned int ticket;
    const int tid = threadIdx.x;
    {
        int e  = (blockIdx.x & 3) * 128 + tid;
        int cg = blockIdx.x >> 2;              // 0..15
        float s = 0.f;
        for (int c = cg * 64; c < cg * 64 + 64; c++)
            s += g_partial[(size_t)c * 512 + e];
        g_partial2[cg * 512 + e] = s;
    }
    __threadfence();
    if (tid == 0) ticket = atomicAdd(&g_cnt, 1u);
    __syncthreads();
    if (ticket != 63) return;

    // last block: finalize
    float myloss = 0.f;
#pragma unroll
    for (int r = 0; r < 4; r++) {
        int e = tid + r * 128;
        float s = 0.f;
#pragma unroll
        for (int b = 0; b < 16; b++) s += g_partial2[b * 512 + e];
        out[1 + e] = s;                                   // probs
        float p = fminf(fmaxf(s, 1e-10f), 1.0f);          // clip
        float t = y_true[e];
        myloss += t * (logf(t + 1e-10f) - logf(p));
    }
    red[tid] = myloss;
    __syncthreads();
    for (int st = 64; st > 0; st >>= 1) {
        if (tid < st) red[tid] += red[tid + st];
        __syncthreads();
    }
    if (tid == 0) { out[0] = red[0]; g_cnt = 0u; }        // d + reset ticket
}

// ---------------- launch ----------------
extern "C" void kernel_launch(void* const* d_in, const int* in_sizes, int n_in,
                              void* d_out, int out_size) {
    const float* y_pred = (const float*)d_in[0];
    const float* y_true = (const float*)d_in[1];
    float* out = (float*)d_out;

    cudaFuncSetAttribute(gemm_kernel, cudaFuncAttributeMaxDynamicSharedMemorySize, SMEM_DYN);

    conv_kernel<<<2560, 256>>>(y_pred);
    gemm_kernel<<<dim3(32, 32), 256, SMEM_DYN>>>(y_pred);
    reduce_final_kernel<<<64, 128>>>(y_true, out);
}